// round 2
// baseline (speedup 1.0000x reference)
#include <cuda_runtime.h>
#include <math.h>

// Problem constants
#define WINDOW 40
#define E 8
#define FDIM 64
#define TDIM 64
#define KERNEL 5
#define IN_CH 144          // F + 10*E
#define LIN_IN 36          // WINDOW + 1 - KERNEL
#define NCOL 320           // WINDOW * E rank columns
#define NMAX 8192

// Scratch (device globals — no allocation allowed)
__device__ float g_cols[(size_t)NCOL * NMAX];  // [col][n]  col-major gather of last window
__device__ float g_rank[(size_t)NMAX * NCOL];  // [n][col]  rank/N, coalesced for main kernel

// ---------------------------------------------------------------------------
// Kernel 1: gather x[:, 24+t, 0:8] -> g_cols[(t*8+f)][n] (one 32B sector per (n,t))
// ---------------------------------------------------------------------------
__global__ void gather_kernel(const float* __restrict__ x, int N) {
    __shared__ float tile[256][9];   // pad 9 -> conflict-free both phases
    const int t  = blockIdx.y;
    const int n0 = blockIdx.x * 256;
    const int tid = threadIdx.x;
    const int n = n0 + tid;
    if (n < N) {
        const float4* p = (const float4*)(x + (size_t)n * (TDIM * FDIM) + (24 + t) * FDIM);
        float4 a = p[0], b = p[1];
        tile[tid][0] = a.x; tile[tid][1] = a.y; tile[tid][2] = a.z; tile[tid][3] = a.w;
        tile[tid][4] = b.x; tile[tid][5] = b.y; tile[tid][6] = b.z; tile[tid][7] = b.w;
    }
    __syncthreads();
    #pragma unroll
    for (int idx = tid; idx < 8 * 256; idx += 256) {
        int f = idx >> 8, s = idx & 255;
        int nn = n0 + s;
        if (nn < N) g_cols[(size_t)(t * 8 + f) * NMAX + nn] = tile[s][f];
    }
}

// ---------------------------------------------------------------------------
// Kernel 2: exact stable descending rank via 14-bit bucket histogram +
//           within-bucket brute-force compare. Bit-exact vs stable radix sort.
// ---------------------------------------------------------------------------
#define RT 512
#define NBIN 16384          // top-14-bit buckets of the descending key

// dynamic smem layout (bytes):
//   u32 keys [NMAX]        : 32768
//   u32 hist [NBIN/2]      : 32768   (u16-pair packed; later reused as scatter cursors)
//   u16 base [NBIN+2]      : 32772
//   u16 order[NMAX]        : 16384
#define RANK_SMEM (32768 + 32768 + 32772 + 16384)

__global__ __launch_bounds__(RT) void rank_kernel(int N) {
    extern __shared__ unsigned char sm_raw[];
    unsigned int*   keys  = (unsigned int*)sm_raw;
    unsigned int*   hist  = (unsigned int*)(sm_raw + 32768);
    unsigned short* base  = (unsigned short*)(sm_raw + 65536);
    unsigned short* order = (unsigned short*)(sm_raw + 65536 + 32772);
    __shared__ unsigned int aux[RT];
    __shared__ unsigned int aux2[16];

    const int c   = blockIdx.x;
    const int tid = threadIdx.x;
    const int lane = tid & 31, wrp = tid >> 5;

    // zero histogram
    #pragma unroll
    for (int i = tid; i < NBIN / 2; i += RT) hist[i] = 0u;
    __syncthreads();

    // load keys (descending-monotone transform) + histogram
    const float* col = &g_cols[(size_t)c * NMAX];
    for (int i = tid; i < N; i += RT) {
        unsigned int u = __float_as_uint(col[i]);
        unsigned int mono = u ^ ((u >> 31) ? 0xFFFFFFFFu : 0x80000000u);
        unsigned int k = ~mono;                 // ascending k == descending value
        keys[i] = k;
        unsigned int b = k >> 18;               // top 14 bits
        atomicAdd(&hist[b >> 1], 1u << ((b & 1) * 16));
    }
    __syncthreads();

    // exclusive scan of 16384 bins (32 bins = 16 packed words per thread)
    unsigned int tsum = 0;
    #pragma unroll
    for (int w = 0; w < 16; ++w) {
        unsigned int v = hist[tid * 16 + w];
        tsum += (v & 0xFFFFu) + (v >> 16);
    }
    // block scan of per-thread sums
    unsigned int v = tsum;
    #pragma unroll
    for (int d = 1; d < 32; d <<= 1) {
        unsigned int t2 = __shfl_up_sync(0xFFFFFFFFu, v, d);
        if (lane >= d) v += t2;
    }
    if (lane == 31) aux2[wrp] = v;
    __syncthreads();
    if (wrp == 0 && lane < 16) {
        unsigned int s = aux2[lane];
        #pragma unroll
        for (int d = 1; d < 16; d <<= 1) {
            unsigned int t2 = __shfl_up_sync(0x0000FFFFu, s, d);
            if (lane >= d) s += t2;
        }
        aux2[lane] = s;
    }
    __syncthreads();
    unsigned int run = v - tsum + (wrp ? aux2[wrp - 1] : 0u);  // exclusive prefix
    // write per-bin exclusive offsets
    #pragma unroll
    for (int w = 0; w < 16; ++w) {
        unsigned int pv = hist[tid * 16 + w];
        unsigned int lo = pv & 0xFFFFu, hi = pv >> 16;
        int b = tid * 32 + w * 2;
        base[b]     = (unsigned short)run;  run += lo;
        base[b + 1] = (unsigned short)run;  run += hi;
    }
    if (tid == 0) { base[NBIN] = (unsigned short)N; base[NBIN + 1] = (unsigned short)N; }
    __syncthreads();
    // reload base into hist as packed running cursors for the scatter
    #pragma unroll
    for (int w = 0; w < NBIN / 2; w += RT) {
        int i = w + tid;
        hist[i] = (unsigned int)base[2 * i] | ((unsigned int)base[2 * i + 1] << 16);
    }
    __syncthreads();

    // scatter element indices into bucket-grouped order[] (unstable is fine)
    for (int i = tid; i < N; i += RT) {
        unsigned int b = keys[i] >> 18;
        unsigned int sh = (b & 1) * 16;
        unsigned int old = atomicAdd(&hist[b >> 1], 1u << sh);
        order[(old >> sh) & 0xFFFFu] = (unsigned short)i;
    }
    __syncthreads();

    // exact rank: base of bucket + within-bucket compares (key, then index)
    const float inv = 1.0f / (float)N;
    for (int i = tid; i < N; i += RT) {
        unsigned int k = keys[i];
        unsigned int b = k >> 18;
        int s = base[b], e = base[b + 1];
        int r = s;
        for (int p = s; p < e; ++p) {
            int j = order[p];
            unsigned int kj = keys[j];
            r += (kj < k) || (kj == k && j < i);
        }
        g_rank[(size_t)i * NCOL + c] = (float)r * inv;
    }
}

// ---------------------------------------------------------------------------
// Kernel 3: per-sample stats + channel-127 conv + leaky + linear
// ---------------------------------------------------------------------------
__global__ __launch_bounds__(320) void main_kernel(
    const float* __restrict__ x, const float* __restrict__ conv_w,
    const float* __restrict__ conv_b, const float* __restrict__ lin_w,
    const float* __restrict__ lin_b, float* __restrict__ out, int N)
{
    __shared__ float xe[59 * 8];         // rows 5..63 of first 8 features
    __shared__ float xc[WINDOW * IN_CH]; // assembled conv input [40][144]
    __shared__ float ws[IN_CH * KERNEL]; // conv_w[127]
    __shared__ float lw[LIN_IN];
    __shared__ float part[LIN_IN];

    const int n   = blockIdx.x;
    const int tid = threadIdx.x;
    const float* xn = x + (size_t)n * (TDIM * FDIM);

    // ---- phase 1: loads ----
    for (int i = tid; i < IN_CH * KERNEL; i += 320) ws[i] = conv_w[127 * IN_CH * KERNEL + i];
    if (tid < LIN_IN) lw[tid] = lin_w[tid];

    for (int i = tid; i < 59 * 8; i += 320) {
        int r = i >> 3, f = i & 7;
        xe[i] = xn[(5 + r) * FDIM + f];
    }
    // raw channels: x[n, 24:64, 0:64] is 2560 contiguous floats
    {
        const float4* src = (const float4*)(xn + 24 * FDIM);
        for (int q = tid; q < 640; q += 320) {
            float4 v = src[q];
            int l = q * 4;
            int t = l >> 6, i = l & 63;
            *(float4*)&xc[t * IN_CH + i] = v;
        }
    }
    // rank (coalesced): identical rank feeds week slot (80..87) and month slot (120..127)
    {
        float r = g_rank[(size_t)n * NCOL + tid];
        int t = tid >> 3, f = tid & 7;
        xc[t * IN_CH + 80 + f]  = r;
        xc[t * IN_CH + 120 + f] = r;
    }
    __syncthreads();

    // ---- phase 2: sliding-window stats (thread = one (t,f) pair) ----
    {
        const int t = tid >> 3, f = tid & 7;
        float* row = &xc[t * IN_CH];
        // week: xe rows 15+t .. 19+t
        float s = 0.f, s2 = 0.f, mx = -1e30f, mn = 1e30f;
        #pragma unroll
        for (int j = 0; j < 5; ++j) {
            float v = xe[(15 + t + j) * 8 + f];
            s += v; s2 = fmaf(v, v, s2);
            mx = fmaxf(mx, v); mn = fminf(mn, v);
        }
        row[64 + f] = s * 0.2f;
        row[72 + f] = sqrtf(fmaxf((s2 - s * s * 0.2f) * 0.25f, 0.f));
        row[88 + f] = mx;
        row[96 + f] = mn;
        // month: xe rows t .. t+19
        s = 0.f; s2 = 0.f; mx = -1e30f; mn = 1e30f;
        #pragma unroll
        for (int j = 0; j < 20; ++j) {
            float v = xe[(t + j) * 8 + f];
            s += v; s2 = fmaf(v, v, s2);
            mx = fmaxf(mx, v); mn = fminf(mn, v);
        }
        row[104 + f] = s * 0.05f;
        row[112 + f] = sqrtf(fmaxf((s2 - s * s * 0.05f) * (1.0f / 19.0f), 0.f));
        row[128 + f] = mx;
        row[136 + f] = mn;
    }
    __syncthreads();

    // ---- phase 3: conv channel 127 (8 lanes per output t, 18 channels each) ----
    float partial = 0.0f;
    if (tid < LIN_IN * 8) {
        const int g = tid & 7, t = tid >> 3;
        const float* xr = &xc[t * IN_CH];
        const int i0 = g * 18;
        #pragma unroll
        for (int ii = 0; ii < 18; ++ii) {
            int i = i0 + ii;
            const float* w = &ws[i * KERNEL];
            float acc = 0.f;
            #pragma unroll
            for (int k = 0; k < KERNEL; ++k)
                acc = fmaf(w[k], xr[k * IN_CH + i], acc);
            partial += acc;
        }
    }
    partial += __shfl_down_sync(0xFFFFFFFFu, partial, 4, 8);
    partial += __shfl_down_sync(0xFFFFFFFFu, partial, 2, 8);
    partial += __shfl_down_sync(0xFFFFFFFFu, partial, 1, 8);
    if ((tid & 7) == 0 && tid < LIN_IN * 8) {
        int t = tid >> 3;
        float s = partial + conv_b[127];
        s = (s >= 0.0f) ? s : 0.01f * s;   // leaky ALPHA=0.01
        part[t] = s * lw[t];
    }
    __syncthreads();
    // final reduction: one warp sums 36 partials
    if (tid < 32) {
        float v = part[tid] + ((tid < 4) ? part[32 + tid] : 0.0f);
        #pragma unroll
        for (int d = 16; d > 0; d >>= 1)
            v += __shfl_down_sync(0xFFFFFFFFu, v, d);
        if (tid == 0) out[n] = v + lin_b[0];
    }
}

// ---------------------------------------------------------------------------
extern "C" void kernel_launch(void* const* d_in, const int* in_sizes, int n_in,
                              void* d_out, int out_size) {
    const float* x      = (const float*)d_in[0];
    const float* conv_w = (const float*)d_in[1];
    const float* conv_b = (const float*)d_in[2];
    const float* lin_w  = (const float*)d_in[3];
    const float* lin_b  = (const float*)d_in[4];
    float* out = (float*)d_out;
    const int N = in_sizes[0] / (TDIM * FDIM);   // 8000

    cudaFuncSetAttribute(rank_kernel, cudaFuncAttributeMaxDynamicSharedMemorySize, RANK_SMEM);

    dim3 gg((N + 255) / 256, WINDOW);
    gather_kernel<<<gg, 256>>>(x, N);
    rank_kernel<<<NCOL, RT, RANK_SMEM>>>(N);
    main_kernel<<<N, 320>>>(x, conv_w, conv_b, lin_w, lin_b, out, N);
}

// round 3
// speedup vs baseline: 1.2238x; 1.2238x over previous
#include <cuda_runtime.h>
#include <math.h>

// Problem constants
#define WINDOW 40
#define E 8
#define FDIM 64
#define TDIM 64
#define KERNEL 5
#define IN_CH 144          // F + 10*E
#define LIN_IN 36          // WINDOW + 1 - KERNEL
#define NCOL 320           // WINDOW * E rank columns
#define NMAX 8192

// Scratch (device global — no allocation allowed)
__device__ float g_rankT[(size_t)NCOL * NMAX];   // [col][n]  rank/N, coalesced writes

// ---------------------------------------------------------------------------
// Rank kernel: one block per column. Loads its column straight from x
// (L2-resident hot region), computes exact stable descending rank via a
// 15-bit bucket histogram + tiny within-bucket compare. Bit-exact vs
// argsort(argsort(-last)).
// ---------------------------------------------------------------------------
#define RT 512
#define NBIN 32768                 // 15-bit buckets of the ascending key
#define HWORDS (NBIN / 2)          // 16384 packed u16-pair words
#define HPHYS  (HWORDS + HWORDS/32)// +1 pad word per 32 -> conflict-free scan

__device__ __forceinline__ int hphys(int W) { return W + (W >> 5); }

// dynamic smem: keys u32[8192] | hist u32[HPHYS] | order u16[8192]
#define RANK_SMEM (32768 + HPHYS * 4 + 16384)

__global__ __launch_bounds__(RT) void rank_kernel(const float* __restrict__ x, int N) {
    extern __shared__ unsigned char sm_raw[];
    unsigned int*   keys  = (unsigned int*)sm_raw;
    unsigned int*   hist  = (unsigned int*)(sm_raw + 32768);
    unsigned short* order = (unsigned short*)(sm_raw + 32768 + HPHYS * 4);
    __shared__ unsigned int aux2[16];

    const int c    = blockIdx.x;
    const int tid  = threadIdx.x;
    const int lane = tid & 31, wrp = tid >> 5;

    // column address: x[n, 24 + (c>>3), c&7]
    const float* colp = x + (size_t)(24 + (c >> 3)) * FDIM + (c & 7);

    // zero histogram
    for (int i = tid; i < HPHYS; i += RT) hist[i] = 0u;
    __syncthreads();

    // load keys (descending-monotone transform) + histogram
    for (int i = tid; i < N; i += RT) {
        unsigned int u = __float_as_uint(__ldg(colp + (size_t)i * (TDIM * FDIM)));
        unsigned int mono = u ^ ((u >> 31) ? 0xFFFFFFFFu : 0x80000000u);
        unsigned int k = ~mono;                 // ascending k == descending value
        keys[i] = k;
        unsigned int b = k >> 17;               // top 15 bits
        atomicAdd(&hist[hphys(b >> 1)], 1u << ((b & 1) * 16));
    }
    __syncthreads();

    // exclusive scan over 32768 bins; thread owns 32 words (64 bins),
    // padded layout -> conflict-free (phys base = tid*33)
    const int base = tid * 33;
    unsigned int tsum = 0;
    #pragma unroll
    for (int w = 0; w < 32; ++w) {
        unsigned int v = hist[base + w];
        tsum += (v & 0xFFFFu) + (v >> 16);
    }
    unsigned int v = tsum;
    #pragma unroll
    for (int d = 1; d < 32; d <<= 1) {
        unsigned int t2 = __shfl_up_sync(0xFFFFFFFFu, v, d);
        if (lane >= d) v += t2;
    }
    if (lane == 31) aux2[wrp] = v;
    __syncthreads();
    if (wrp == 0 && lane < 16) {
        unsigned int s = aux2[lane];
        #pragma unroll
        for (int d = 1; d < 16; d <<= 1) {
            unsigned int t2 = __shfl_up_sync(0x0000FFFFu, s, d);
            if (lane >= d) s += t2;
        }
        aux2[lane] = s;
    }
    __syncthreads();
    unsigned int run = v - tsum + (wrp ? aux2[wrp - 1] : 0u);  // exclusive prefix
    #pragma unroll
    for (int w = 0; w < 32; ++w) {
        unsigned int pv = hist[base + w];
        unsigned int lo = pv & 0xFFFFu, hi = pv >> 16;
        hist[base + w] = run | ((run + lo) << 16);   // packed bucket-start cursors
        run += lo + hi;
    }
    __syncthreads();

    // scatter indices into bucket-grouped order[] (unstable is fine);
    // afterwards cursor[b] == end-of-bucket-b == start-of-bucket-(b+1)
    for (int i = tid; i < N; i += RT) {
        unsigned int b = keys[i] >> 17;
        unsigned int sh = (b & 1) * 16;
        unsigned int old = atomicAdd(&hist[hphys(b >> 1)], 1u << sh);
        order[(old >> sh) & 0xFFFFu] = (unsigned short)i;
    }
    __syncthreads();

    // exact rank: start-of-bucket + within-bucket compares (key, then index)
    const float inv = 1.0f / (float)N;
    float* dst = &g_rankT[(size_t)c * NMAX];
    for (int i = tid; i < N; i += RT) {
        unsigned int k = keys[i];
        unsigned int b = k >> 17;
        unsigned int we = hist[hphys(b >> 1)];
        int e = (we >> ((b & 1) * 16)) & 0xFFFFu;
        int s = 0;
        if (b) {
            unsigned int b1 = b - 1;
            unsigned int ws = hist[hphys(b1 >> 1)];
            s = (ws >> ((b1 & 1) * 16)) & 0xFFFFu;
        }
        int r = s;
        for (int p = s; p < e; ++p) {
            int j = order[p];
            unsigned int kj = keys[j];
            r += (kj < k) || (kj == k && j < i);
        }
        dst[i] = (float)r * inv;        // coalesced
    }
}

// ---------------------------------------------------------------------------
// Main kernel: per-sample stats + channel-127 conv + leaky + linear
// (only conv output channel 127 feeds the result; rest of the conv is dead)
// ---------------------------------------------------------------------------
__global__ __launch_bounds__(320) void main_kernel(
    const float* __restrict__ x, const float* __restrict__ conv_w,
    const float* __restrict__ conv_b, const float* __restrict__ lin_w,
    const float* __restrict__ lin_b, float* __restrict__ out, int N)
{
    __shared__ float xe[59 * 8];         // rows 5..63 of first 8 features
    __shared__ float xc[WINDOW * IN_CH]; // assembled conv input [40][144]
    __shared__ float ws[IN_CH * KERNEL]; // conv_w[127]
    __shared__ float lw[LIN_IN];
    __shared__ float part[LIN_IN];

    const int n   = blockIdx.x;
    const int tid = threadIdx.x;
    const float* xn = x + (size_t)n * (TDIM * FDIM);

    // ---- phase 1: loads ----
    for (int i = tid; i < IN_CH * KERNEL; i += 320) ws[i] = conv_w[127 * IN_CH * KERNEL + i];
    if (tid < LIN_IN) lw[tid] = lin_w[tid];

    for (int i = tid; i < 59 * 8; i += 320) {
        int r = i >> 3, f = i & 7;
        xe[i] = xn[(5 + r) * FDIM + f];
    }
    // raw channels: x[n, 24:64, 0:64] is 2560 contiguous floats
    {
        const float4* src = (const float4*)(xn + 24 * FDIM);
        for (int q = tid; q < 640; q += 320) {
            float4 v = src[q];
            int l = q * 4;
            int t = l >> 6, i = l & 63;
            *(float4*)&xc[t * IN_CH + i] = v;
        }
    }
    // rank (L2-resident): identical rank feeds week slot (80..87) and month (120..127)
    {
        float r = __ldg(&g_rankT[(size_t)tid * NMAX + n]);
        int t = tid >> 3, f = tid & 7;
        xc[t * IN_CH + 80 + f]  = r;
        xc[t * IN_CH + 120 + f] = r;
    }
    __syncthreads();

    // ---- phase 2: sliding-window stats (thread = one (t,f) pair) ----
    {
        const int t = tid >> 3, f = tid & 7;
        float* row = &xc[t * IN_CH];
        // week: xe rows 15+t .. 19+t
        float s = 0.f, s2 = 0.f, mx = -1e30f, mn = 1e30f;
        #pragma unroll
        for (int j = 0; j < 5; ++j) {
            float v = xe[(15 + t + j) * 8 + f];
            s += v; s2 = fmaf(v, v, s2);
            mx = fmaxf(mx, v); mn = fminf(mn, v);
        }
        row[64 + f] = s * 0.2f;
        row[72 + f] = sqrtf(fmaxf((s2 - s * s * 0.2f) * 0.25f, 0.f));
        row[88 + f] = mx;
        row[96 + f] = mn;
        // month: xe rows t .. t+19
        s = 0.f; s2 = 0.f; mx = -1e30f; mn = 1e30f;
        #pragma unroll
        for (int j = 0; j < 20; ++j) {
            float v = xe[(t + j) * 8 + f];
            s += v; s2 = fmaf(v, v, s2);
            mx = fmaxf(mx, v); mn = fminf(mn, v);
        }
        row[104 + f] = s * 0.05f;
        row[112 + f] = sqrtf(fmaxf((s2 - s * s * 0.05f) * (1.0f / 19.0f), 0.f));
        row[128 + f] = mx;
        row[136 + f] = mn;
    }
    __syncthreads();

    // ---- phase 3: conv channel 127 (8 lanes per output t, 18 channels each) ----
    float partial = 0.0f;
    if (tid < LIN_IN * 8) {
        const int g = tid & 7, t = tid >> 3;
        const float* xr = &xc[t * IN_CH];
        const int i0 = g * 18;
        #pragma unroll
        for (int ii = 0; ii < 18; ++ii) {
            int i = i0 + ii;
            const float* w = &ws[i * KERNEL];
            float acc = 0.f;
            #pragma unroll
            for (int k = 0; k < KERNEL; ++k)
                acc = fmaf(w[k], xr[k * IN_CH + i], acc);
            partial += acc;
        }
    }
    partial += __shfl_down_sync(0xFFFFFFFFu, partial, 4, 8);
    partial += __shfl_down_sync(0xFFFFFFFFu, partial, 2, 8);
    partial += __shfl_down_sync(0xFFFFFFFFu, partial, 1, 8);
    if ((tid & 7) == 0 && tid < LIN_IN * 8) {
        int t = tid >> 3;
        float s = partial + conv_b[127];
        s = (s >= 0.0f) ? s : 0.01f * s;   // leaky ALPHA=0.01
        part[t] = s * lw[t];
    }
    __syncthreads();
    // final reduction: one warp sums 36 partials
    if (tid < 32) {
        float v = part[tid] + ((tid < 4) ? part[32 + tid] : 0.0f);
        #pragma unroll
        for (int d = 16; d > 0; d >>= 1)
            v += __shfl_down_sync(0xFFFFFFFFu, v, d);
        if (tid == 0) out[n] = v + lin_b[0];
    }
}

// ---------------------------------------------------------------------------
extern "C" void kernel_launch(void* const* d_in, const int* in_sizes, int n_in,
                              void* d_out, int out_size) {
    const float* x      = (const float*)d_in[0];
    const float* conv_w = (const float*)d_in[1];
    const float* conv_b = (const float*)d_in[2];
    const float* lin_w  = (const float*)d_in[3];
    const float* lin_b  = (const float*)d_in[4];
    float* out = (float*)d_out;
    const int N = in_sizes[0] / (TDIM * FDIM);   // 8000

    cudaFuncSetAttribute(rank_kernel, cudaFuncAttributeMaxDynamicSharedMemorySize, RANK_SMEM);

    rank_kernel<<<NCOL, RT, RANK_SMEM>>>(x, N);
    main_kernel<<<N, 320>>>(x, conv_w, conv_b, lin_w, lin_b, out, N);
}